// round 2
// baseline (speedup 1.0000x reference)
#include <cuda_runtime.h>
#include <math.h>

#define EMB   1024
#define HD    64
#define NH    16
#define SEQ   2048
#define BATCH 2
#define MROWS (BATCH*SEQ)          // 4096
#define QKV_ELEMS (BATCH*NH*SEQ*HD)

// ---- scratch (allocation-free: __device__ globals) ----
__device__ float g_Q[QKV_ELEMS];
__device__ float g_K[QKV_ELEMS];
__device__ float g_V[QKV_ELEMS];
__device__ float g_O[QKV_ELEMS];
__device__ float g_partial[NH * 16];
__device__ float g_scale[NH];
__device__ float g_bias[EMB];

// ============================================================
// Kernel 1: QKV projection GEMM.
// C[4096,1024] = X[4096,1024] @ W + bias, W logical [E, H*hd] stored as [H,E,hd].
// Output written in [B,H,T,hd] layout. blockIdx.z in {0,1,2} = Q,K,V.
// Tiles: BM=BN=128, BK=16, 256 threads, 8x8 per thread (2x2 quadrants of 4).
// ============================================================
__global__ __launch_bounds__(256)
void qkv_gemm(const float* __restrict__ X,
              const float* __restrict__ Wq, const float* __restrict__ bq,
              const float* __restrict__ Wk, const float* __restrict__ bk,
              const float* __restrict__ Wv, const float* __restrict__ bv)
{
    const int z = blockIdx.z;
    const float* W    = (z == 0) ? Wq : (z == 1) ? Wk : Wv;
    const float* bias = (z == 0) ? bq : (z == 1) ? bk : bv;
    float* OUT        = (z == 0) ? g_Q : (z == 1) ? g_K : g_V;

    __shared__ float As[16][128];   // k-major (transposed A tile)
    __shared__ float Bs[16][128];

    const int m0  = blockIdx.y * 128;
    const int n0  = blockIdx.x * 128;
    const int tid = threadIdx.x;
    const int tx  = tid & 15;
    const int ty  = tid >> 4;

    float acc[8][8];
    #pragma unroll
    for (int i = 0; i < 8; i++)
        #pragma unroll
        for (int j = 0; j < 8; j++) acc[i][j] = 0.f;

    for (int k0 = 0; k0 < EMB; k0 += 16) {
        // load A tile (128 rows x 16 k), transpose into As[k][m]
        #pragma unroll
        for (int i = 0; i < 2; i++) {
            int f    = tid + i * 256;          // float4 id, 512 total
            int arow = f >> 2;
            int ac   = (f & 3) * 4;
            float4 v = *(const float4*)&X[(m0 + arow) * EMB + k0 + ac];
            As[ac + 0][arow] = v.x;
            As[ac + 1][arow] = v.y;
            As[ac + 2][arow] = v.z;
            As[ac + 3][arow] = v.w;
        }
        // load B tile (16 k x 128 cols); W element (d, c=(h,e)) at h*E*hd + d*hd + e
        #pragma unroll
        for (int i = 0; i < 2; i++) {
            int f    = tid + i * 256;
            int brow = f >> 5;
            int bc   = (f & 31) * 4;
            int c    = n0 + bc;
            int h    = c >> 6;
            int e    = c & 63;
            float4 v = *(const float4*)&W[h * (EMB * HD) + (k0 + brow) * HD + e];
            *(float4*)&Bs[brow][bc] = v;
        }
        __syncthreads();

        #pragma unroll
        for (int k = 0; k < 16; k++) {
            float a[8], b[8];
            #pragma unroll
            for (int i = 0; i < 4; i++) {
                a[i]     = As[k][ty * 4 + i];
                a[i + 4] = As[k][64 + ty * 4 + i];
                b[i]     = Bs[k][tx * 4 + i];
                b[i + 4] = Bs[k][64 + tx * 4 + i];
            }
            #pragma unroll
            for (int i = 0; i < 8; i++)
                #pragma unroll
                for (int j = 0; j < 8; j++)
                    acc[i][j] += a[i] * b[j];
        }
        __syncthreads();
    }

    // epilogue: remap (r,c) -> [B,H,T,hd], add bias (bias linear in c)
    #pragma unroll
    for (int i = 0; i < 8; i++) {
        int r  = m0 + ((i < 4) ? (ty * 4 + i) : (64 + ty * 4 + (i - 4)));
        int bb = r >> 11;
        int t  = r & 2047;
        #pragma unroll
        for (int j = 0; j < 8; j++) {
            int c = n0 + ((j < 4) ? (tx * 4 + j) : (64 + tx * 4 + (j - 4)));
            int h = c >> 6;
            int e = c & 63;
            OUT[((bb * NH + h) * SEQ + t) * HD + e] = acc[i][j] + bias[c];
        }
    }
}

// ============================================================
// Kernel 2: flash attention per (b,h). 64-row Q blocks, 64-col KV tiles.
// smem operand tiles stored k-major; P tile reuses the K buffer.
// ============================================================
__global__ __launch_bounds__(256)
void attn_kernel(const float* __restrict__ mask)
{
    __shared__ float Qs [64][64];   // [e][m]
    __shared__ float KPs[64][64];   // K as [e][s], then P as [r][s]
    __shared__ float Vs [64][64];   // [s][e]

    const int mblk = blockIdx.x;    // 0..31
    const int h    = blockIdx.y;
    const int b    = blockIdx.z;
    const int tid  = threadIdx.x;
    const int tx   = tid & 15;
    const int ty   = tid >> 4;

    const float* Q = g_Q + (size_t)(b * NH + h) * SEQ * HD;
    const float* K = g_K + (size_t)(b * NH + h) * SEQ * HD;
    const float* V = g_V + (size_t)(b * NH + h) * SEQ * HD;
    float*       O = g_O + (size_t)(b * NH + h) * SEQ * HD;

    const int t0 = mblk * 64;

    // load Q tile transposed: Qs[e][m]
    #pragma unroll
    for (int i = 0; i < 4; i++) {
        int f   = tid + i * 256;          // 1024 float4
        int row = f >> 4;                 // 0..63 (query row)
        int c   = (f & 15) * 4;           // 0..60 (head dim)
        float4 v = *(const float4*)&Q[(t0 + row) * HD + c];
        Qs[c + 0][row] = v.x;
        Qs[c + 1][row] = v.y;
        Qs[c + 2][row] = v.z;
        Qs[c + 3][row] = v.w;
    }

    float m_i[4], l_i[4], o[4][4];
    #pragma unroll
    for (int i = 0; i < 4; i++) {
        m_i[i] = -INFINITY;
        l_i[i] = 0.f;
        #pragma unroll
        for (int j = 0; j < 4; j++) o[i][j] = 0.f;
    }

    for (int s0 = 0; s0 < SEQ; s0 += 64) {
        __syncthreads();   // previous PV done (and Q visible on first iter)

        // load K transposed into KPs[e][s], V direct into Vs[s][e]
        #pragma unroll
        for (int i = 0; i < 4; i++) {
            int f   = tid + i * 256;
            int row = f >> 4;
            int c   = (f & 15) * 4;
            float4 kv = *(const float4*)&K[(s0 + row) * HD + c];
            KPs[c + 0][row] = kv.x;
            KPs[c + 1][row] = kv.y;
            KPs[c + 2][row] = kv.z;
            KPs[c + 3][row] = kv.w;
            float4 vv = *(const float4*)&V[(s0 + row) * HD + c];
            *(float4*)&Vs[row][c] = vv;
        }
        __syncthreads();

        // S = Q K^T  (per-thread 4x4: rows ty*4+i, cols tx*4+j)
        float sc[4][4];
        #pragma unroll
        for (int i = 0; i < 4; i++)
            #pragma unroll
            for (int j = 0; j < 4; j++) sc[i][j] = 0.f;

        #pragma unroll 8
        for (int k = 0; k < 64; k++) {
            float4 av = *(const float4*)&Qs [k][ty * 4];
            float4 bv = *(const float4*)&KPs[k][tx * 4];
            float a[4] = {av.x, av.y, av.z, av.w};
            float bb2[4] = {bv.x, bv.y, bv.z, bv.w};
            #pragma unroll
            for (int i = 0; i < 4; i++)
                #pragma unroll
                for (int j = 0; j < 4; j++)
                    sc[i][j] += a[i] * bb2[j];
        }

        // scale + mask
        #pragma unroll
        for (int i = 0; i < 4; i++) {
            const float* mrow = &mask[(size_t)(t0 + ty * 4 + i) * SEQ + s0 + tx * 4];
            #pragma unroll
            for (int j = 0; j < 4; j++)
                sc[i][j] = sc[i][j] * 0.125f + mrow[j];
        }

        // online softmax (row stats replicated across the 16-lane tx group)
        #pragma unroll
        for (int i = 0; i < 4; i++) {
            float rm = fmaxf(fmaxf(sc[i][0], sc[i][1]), fmaxf(sc[i][2], sc[i][3]));
            #pragma unroll
            for (int off = 1; off < 16; off <<= 1)
                rm = fmaxf(rm, __shfl_xor_sync(0xffffffffu, rm, off));
            float mnew = fmaxf(m_i[i], rm);
            float corr = __expf(m_i[i] - mnew);
            float rs = 0.f;
            #pragma unroll
            for (int j = 0; j < 4; j++) {
                float p = __expf(sc[i][j] - mnew);
                sc[i][j] = p;
                rs += p;
            }
            #pragma unroll
            for (int off = 1; off < 16; off <<= 1)
                rs += __shfl_xor_sync(0xffffffffu, rs, off);
            l_i[i] = l_i[i] * corr + rs;
            m_i[i] = mnew;
            #pragma unroll
            for (int j = 0; j < 4; j++) o[i][j] *= corr;
        }

        __syncthreads();   // all reads of KPs-as-K complete

        // store P into KPs as [r][s]
        #pragma unroll
        for (int i = 0; i < 4; i++)
            #pragma unroll
            for (int j = 0; j < 4; j++)
                KPs[ty * 4 + i][tx * 4 + j] = sc[i][j];
        __syncthreads();

        // O += P V
        #pragma unroll 8
        for (int s = 0; s < 64; s++) {
            float4 vv = *(const float4*)&Vs[s][tx * 4];
            float v4[4] = {vv.x, vv.y, vv.z, vv.w};
            float p0 = KPs[ty * 4 + 0][s];
            float p1 = KPs[ty * 4 + 1][s];
            float p2 = KPs[ty * 4 + 2][s];
            float p3 = KPs[ty * 4 + 3][s];
            #pragma unroll
            for (int j = 0; j < 4; j++) {
                o[0][j] += p0 * v4[j];
                o[1][j] += p1 * v4[j];
                o[2][j] += p2 * v4[j];
                o[3][j] += p3 * v4[j];
            }
        }
    }

    // finalize and write out (raw O; norm folded in later)
    #pragma unroll
    for (int i = 0; i < 4; i++) {
        float inv = 1.f / l_i[i];
        int t = t0 + ty * 4 + i;
        #pragma unroll
        for (int j = 0; j < 4; j++)
            O[t * HD + tx * 4 + j] = o[i][j] * inv;
    }
}

// ============================================================
// Kernel 3: per-head norm partial sums (deterministic 2-stage reduce).
// grid (16 chunks, NH heads), 256 threads, one row per thread.
// ============================================================
__global__ __launch_bounds__(256)
void norm_partial()
{
    const int c   = blockIdx.x;
    const int h   = blockIdx.y;
    const int tid = threadIdx.x;
    const int bt  = c * 256 + tid;          // 0..4095
    const int b   = bt >> 11;
    const int t   = bt & 2047;

    const float* row = g_O + (size_t)((b * NH + h) * SEQ + t) * HD;
    float ss = 0.f;
    #pragma unroll
    for (int i = 0; i < 16; i++) {
        float4 v = *(const float4*)&row[i * 4];
        ss += v.x * v.x + v.y * v.y + v.z * v.z + v.w * v.w;
    }
    float nrm = sqrtf(ss);

    __shared__ float red[256];
    red[tid] = nrm;
    __syncthreads();
    for (int s = 128; s > 0; s >>= 1) {
        if (tid < s) red[tid] += red[tid + s];
        __syncthreads();
    }
    if (tid == 0) g_partial[h * 16 + c] = red[0];
}

// ============================================================
// Kernel 4: finalize per-head scale g/(denom*H) and fused output bias.
// ============================================================
__global__ void finalize(const float* __restrict__ gate,
                         const float* __restrict__ b_o)
{
    const int tid = threadIdx.x;   // 1024 threads
    if (tid < NH) {
        float s = 0.f;
        #pragma unroll
        for (int c = 0; c < 16; c++) s += g_partial[tid * 16 + c];
        float denom = fmaxf(s / (float)MROWS, 1e-5f);
        float g = fminf(fmaxf(gate[tid], 0.f), 1.f);
        g_scale[tid] = g / (denom * (float)NH);
    }
    float bsum = 0.f;
    #pragma unroll
    for (int h = 0; h < NH; h++) {
        float g = fminf(fmaxf(gate[h], 0.f), 1.f);
        bsum += g * b_o[h * EMB + tid];
    }
    g_bias[tid] = bsum / (float)NH;
}

// ============================================================
// Kernel 5: output projection GEMM.
// A[r,k=(h,e)] = g_O[b,h,t,e] * g_scale[h];  B = W_o linear [1024,1024];
// C = d_out[r,d] + g_bias[d].
// ============================================================
__global__ __launch_bounds__(256)
void out_gemm(const float* __restrict__ Wo, float* __restrict__ OUTP)
{
    __shared__ float As[16][128];
    __shared__ float Bs[16][128];

    const int m0  = blockIdx.y * 128;
    const int n0  = blockIdx.x * 128;
    const int tid = threadIdx.x;
    const int tx  = tid & 15;
    const int ty  = tid >> 4;

    float acc[8][8];
    #pragma unroll
    for (int i = 0; i < 8; i++)
        #pragma unroll
        for (int j = 0; j < 8; j++) acc[i][j] = 0.f;

    for (int k0 = 0; k0 < EMB; k0 += 16) {
        // A tile with remap + per-head scale
        #pragma unroll
        for (int i = 0; i < 2; i++) {
            int f    = tid + i * 256;
            int arow = f >> 2;
            int ac   = (f & 3) * 4;
            int r    = m0 + arow;
            int k    = k0 + ac;
            int hh   = k >> 6;
            float s  = g_scale[hh];
            const float* src = &g_O[(size_t)(((r >> 11) * NH + hh) * SEQ + (r & 2047)) * HD + (k & 63)];
            float4 v = *(const float4*)src;
            As[ac + 0][arow] = v.x * s;
            As[ac + 1][arow] = v.y * s;
            As[ac + 2][arow] = v.z * s;
            As[ac + 3][arow] = v.w * s;
        }
        // B tile: W_o is [H,hd,E] = linear [k,d]
        #pragma unroll
        for (int i = 0; i < 2; i++) {
            int f    = tid + i * 256;
            int brow = f >> 5;
            int bc   = (f & 31) * 4;
            float4 v = *(const float4*)&Wo[(size_t)(k0 + brow) * EMB + n0 + bc];
            *(float4*)&Bs[brow][bc] = v;
        }
        __syncthreads();

        #pragma unroll
        for (int k = 0; k < 16; k++) {
            float a[8], b[8];
            #pragma unroll
            for (int i = 0; i < 4; i++) {
                a[i]     = As[k][ty * 4 + i];
                a[i + 4] = As[k][64 + ty * 4 + i];
                b[i]     = Bs[k][tx * 4 + i];
                b[i + 4] = Bs[k][64 + tx * 4 + i];
            }
            #pragma unroll
            for (int i = 0; i < 8; i++)
                #pragma unroll
                for (int j = 0; j < 8; j++)
                    acc[i][j] += a[i] * b[j];
        }
        __syncthreads();
    }

    #pragma unroll
    for (int i = 0; i < 8; i++) {
        int r = m0 + ((i < 4) ? (ty * 4 + i) : (64 + ty * 4 + (i - 4)));
        #pragma unroll
        for (int j = 0; j < 8; j++) {
            int c = n0 + ((j < 4) ? (tx * 4 + j) : (64 + tx * 4 + (j - 4)));
            OUTP[(size_t)r * EMB + c] = acc[i][j] + g_bias[c];
        }
    }
}

// ============================================================
extern "C" void kernel_launch(void* const* d_in, const int* in_sizes, int n_in,
                              void* d_out, int out_size)
{
    const float* X    = (const float*)d_in[0];
    const float* mask = (const float*)d_in[1];
    const float* Wq   = (const float*)d_in[2];
    const float* bq   = (const float*)d_in[3];
    const float* Wk   = (const float*)d_in[4];
    const float* bk   = (const float*)d_in[5];
    const float* Wv   = (const float*)d_in[6];
    const float* bv   = (const float*)d_in[7];
    const float* Wo   = (const float*)d_in[8];
    const float* bo   = (const float*)d_in[9];
    const float* gate = (const float*)d_in[10];
    float* out        = (float*)d_out;

    qkv_gemm   <<<dim3(EMB / 128, MROWS / 128, 3), 256>>>(X, Wq, bq, Wk, bk, Wv, bv);
    attn_kernel<<<dim3(SEQ / 64, NH, BATCH),       256>>>(mask);
    norm_partial<<<dim3(16, NH),                   256>>>();
    finalize   <<<1, EMB>>>(gate, bo);
    out_gemm   <<<dim3(EMB / 128, MROWS / 128),    256>>>(Wo, out);
}

// round 3
// speedup vs baseline: 2.6131x; 2.6131x over previous
#include <cuda_runtime.h>
#include <math.h>

#define EMB   1024
#define HD    64
#define NH    16
#define SEQ   2048
#define BATCH 2
#define MROWS (BATCH*SEQ)          // 4096
#define QKV_ELEMS (BATCH*NH*SEQ*HD)

// ---- scratch (allocation-free: __device__ globals) ----
__device__ float g_Q[QKV_ELEMS];
__device__ float g_K[QKV_ELEMS];
__device__ float g_V[QKV_ELEMS];
__device__ float g_O[QKV_ELEMS];
__device__ float g_partial[NH * 16];
__device__ float g_scale[NH];
__device__ float g_bias[EMB];

// ---- tf32 helpers ----
__device__ __forceinline__ float tf32r(float x) {
    unsigned u;
    asm("cvt.rna.tf32.f32 %0, %1;" : "=r"(u) : "f"(x));
    return __uint_as_float(u);
}
__device__ __forceinline__ unsigned fbits(float x) { return __float_as_uint(x); }

// D += A(16x8, row) * B(8x8, col) ; tf32 operands, fp32 accum
__device__ __forceinline__ void mma8(float c[4], const unsigned a[4],
                                     unsigned b0, unsigned b1) {
    asm volatile(
        "mma.sync.aligned.m16n8k8.row.col.f32.tf32.tf32.f32 "
        "{%0,%1,%2,%3},{%4,%5,%6,%7},{%8,%9},{%0,%1,%2,%3};"
        : "+f"(c[0]), "+f"(c[1]), "+f"(c[2]), "+f"(c[3])
        : "r"(a[0]), "r"(a[1]), "r"(a[2]), "r"(a[3]), "r"(b0), "r"(b1));
}

// ============================================================
// Kernel 1: QKV projection GEMM (tf32 tensor cores).
// C[4096,1024] = X @ W + bias; W stored [H,E,hd]; out -> [B,H,T,hd].
// Block 128x128, BK=16, 8 warps (2x4), warp tile 64x32.
// ============================================================
__global__ __launch_bounds__(256)
void qkv_gemm(const float* __restrict__ X,
              const float* __restrict__ Wq, const float* __restrict__ bq,
              const float* __restrict__ Wk, const float* __restrict__ bk,
              const float* __restrict__ Wv, const float* __restrict__ bv)
{
    const int z = blockIdx.z;
    const float* W    = (z == 0) ? Wq : (z == 1) ? Wk : Wv;
    const float* bias = (z == 0) ? bq : (z == 1) ? bk : bv;
    float* OUT        = (z == 0) ? g_Q : (z == 1) ? g_K : g_V;

    __shared__ float As[128][20];    // m-major, k padded 16->20
    __shared__ float Bs[16][136];    // k-major, n padded 128->136

    const int m0   = blockIdx.y * 128;
    const int n0   = blockIdx.x * 128;
    const int tid  = threadIdx.x;
    const int warp = tid >> 5;
    const int lane = tid & 31;
    const int lr   = lane >> 2;      // 0..7
    const int lc   = lane & 3;       // 0..3
    const int wm   = (warp >> 2) * 64;
    const int wn   = (warp & 3) * 32;

    float c[4][4][4];
    #pragma unroll
    for (int mt = 0; mt < 4; mt++)
        #pragma unroll
        for (int nt = 0; nt < 4; nt++)
            #pragma unroll
            for (int r = 0; r < 4; r++) c[mt][nt][r] = 0.f;

    for (int k0 = 0; k0 < EMB; k0 += 16) {
        // A tile: 128 rows x 16 k, m-major
        #pragma unroll
        for (int i = 0; i < 2; i++) {
            int f    = tid + i * 256;
            int arow = f >> 2;
            int ac   = (f & 3) * 4;
            float4 v = *(const float4*)&X[(size_t)(m0 + arow) * EMB + k0 + ac];
            As[arow][ac + 0] = tf32r(v.x);
            As[arow][ac + 1] = tf32r(v.y);
            As[arow][ac + 2] = tf32r(v.z);
            As[arow][ac + 3] = tf32r(v.w);
        }
        // B tile: 16 k x 128 n ; W element (k, c=(h,e)) at h*E*hd + k*hd + e
        #pragma unroll
        for (int i = 0; i < 2; i++) {
            int f    = tid + i * 256;
            int brow = f >> 5;
            int bc   = (f & 31) * 4;
            int cc   = n0 + bc;
            int hh   = cc >> 6;
            int e    = cc & 63;
            float4 v = *(const float4*)&W[(size_t)hh * (EMB * HD) + (size_t)(k0 + brow) * HD + e];
            Bs[brow][bc + 0] = tf32r(v.x);
            Bs[brow][bc + 1] = tf32r(v.y);
            Bs[brow][bc + 2] = tf32r(v.z);
            Bs[brow][bc + 3] = tf32r(v.w);
        }
        __syncthreads();

        #pragma unroll
        for (int kk = 0; kk < 2; kk++) {
            const int klo = kk * 8;
            unsigned a[4][4], bf[4][2];
            #pragma unroll
            for (int mt = 0; mt < 4; mt++) {
                int mr = wm + mt * 16 + lr;
                a[mt][0] = fbits(As[mr    ][klo + lc    ]);
                a[mt][1] = fbits(As[mr + 8][klo + lc    ]);
                a[mt][2] = fbits(As[mr    ][klo + lc + 4]);
                a[mt][3] = fbits(As[mr + 8][klo + lc + 4]);
            }
            #pragma unroll
            for (int nt = 0; nt < 4; nt++) {
                int nn = wn + nt * 8 + lr;
                bf[nt][0] = fbits(Bs[klo + lc    ][nn]);
                bf[nt][1] = fbits(Bs[klo + lc + 4][nn]);
            }
            #pragma unroll
            for (int mt = 0; mt < 4; mt++)
                #pragma unroll
                for (int nt = 0; nt < 4; nt++)
                    mma8(c[mt][nt], a[mt], bf[nt][0], bf[nt][1]);
        }
        __syncthreads();
    }

    // epilogue: remap to [B,H,T,hd], add bias
    #pragma unroll
    for (int mt = 0; mt < 4; mt++) {
        int row0 = m0 + wm + mt * 16 + lr;
        int row1 = row0 + 8;
        int b0i  = row0 >> 11, t0i = row0 & 2047;
        int b1i  = row1 >> 11, t1i = row1 & 2047;
        #pragma unroll
        for (int nt = 0; nt < 4; nt++) {
            int col = n0 + wn + nt * 8 + 2 * lc;
            int hh  = col >> 6;
            int e   = col & 63;
            float2 v0 = make_float2(c[mt][nt][0] + bias[col], c[mt][nt][1] + bias[col + 1]);
            float2 v1 = make_float2(c[mt][nt][2] + bias[col], c[mt][nt][3] + bias[col + 1]);
            *(float2*)&OUT[(size_t)((b0i * NH + hh) * SEQ + t0i) * HD + e] = v0;
            *(float2*)&OUT[(size_t)((b1i * NH + hh) * SEQ + t1i) * HD + e] = v1;
        }
    }
}

// ============================================================
// Kernel 2: flash attention per (b,h), tf32 tensor cores.
// 64 Q rows per block, 4 warps (each owns m16), KV tiles of 64.
// Q fragments register-resident; P reuses the K smem buffer.
// ============================================================
__global__ __launch_bounds__(128)
void attn_kernel(const float* __restrict__ mask)
{
    __shared__ float Ks[64][68];    // K tile [s][e], then P tile [m][s]
    __shared__ float Vs[64][72];    // V tile [s][e]

    const int mblk = blockIdx.x;
    const int h    = blockIdx.y;
    const int b    = blockIdx.z;
    const int tid  = threadIdx.x;
    const int warp = tid >> 5;
    const int lane = tid & 31;
    const int lr   = lane >> 2;
    const int lc   = lane & 3;
    const int wm   = warp * 16;     // warp's row base within 64

    const float* Q = g_Q + (size_t)(b * NH + h) * SEQ * HD;
    const float* K = g_K + (size_t)(b * NH + h) * SEQ * HD;
    const float* V = g_V + (size_t)(b * NH + h) * SEQ * HD;
    float*       O = g_O + (size_t)(b * NH + h) * SEQ * HD;

    const int t0 = mblk * 64;

    // Q fragments: m16 x k64 per warp (rows t0+wm+lr / +8)
    unsigned qa[8][4];
    {
        const float* qp0 = Q + (size_t)(t0 + wm + lr) * HD;
        const float* qp1 = qp0 + 8 * HD;
        #pragma unroll
        for (int k8 = 0; k8 < 8; k8++) {
            int e = k8 * 8;
            qa[k8][0] = fbits(tf32r(qp0[e + lc    ]));
            qa[k8][1] = fbits(tf32r(qp1[e + lc    ]));
            qa[k8][2] = fbits(tf32r(qp0[e + lc + 4]));
            qa[k8][3] = fbits(tf32r(qp1[e + lc + 4]));
        }
    }

    float m_i[2] = {-INFINITY, -INFINITY};
    float l_i[2] = {0.f, 0.f};
    float o[8][4];
    #pragma unroll
    for (int nt = 0; nt < 8; nt++)
        #pragma unroll
        for (int r = 0; r < 4; r++) o[nt][r] = 0.f;

    const float* mrowA = mask + (size_t)(t0 + wm + lr) * SEQ;
    const float* mrowB = mrowA + (size_t)8 * SEQ;

    for (int s0 = 0; s0 < SEQ; s0 += 64) {
        __syncthreads();   // prev PV reads of Ks/Vs complete

        // load K -> Ks[s][e], V -> Vs[s][e] (tf32-rounded)
        #pragma unroll
        for (int i = 0; i < 8; i++) {
            int f   = tid + i * 128;     // 0..1023
            int row = f >> 4;
            int col = (f & 15) * 4;
            float4 kv = *(const float4*)&K[(size_t)(s0 + row) * HD + col];
            Ks[row][col + 0] = tf32r(kv.x);
            Ks[row][col + 1] = tf32r(kv.y);
            Ks[row][col + 2] = tf32r(kv.z);
            Ks[row][col + 3] = tf32r(kv.w);
            float4 vv = *(const float4*)&V[(size_t)(s0 + row) * HD + col];
            Vs[row][col + 0] = tf32r(vv.x);
            Vs[row][col + 1] = tf32r(vv.y);
            Vs[row][col + 2] = tf32r(vv.z);
            Vs[row][col + 3] = tf32r(vv.w);
        }
        __syncthreads();

        // S = Q K^T : per-warp 16x64, 8 n-tiles
        float sc[8][4];
        #pragma unroll
        for (int nt = 0; nt < 8; nt++)
            #pragma unroll
            for (int r = 0; r < 4; r++) sc[nt][r] = 0.f;

        #pragma unroll
        for (int k8 = 0; k8 < 8; k8++) {
            int e = k8 * 8;
            #pragma unroll
            for (int nt = 0; nt < 8; nt++) {
                int s = nt * 8 + lr;
                unsigned b0 = fbits(Ks[s][e + lc    ]);
                unsigned b1 = fbits(Ks[s][e + lc + 4]);
                mma8(sc[nt], qa[k8], b0, b1);
            }
        }

        // scale + mask
        #pragma unroll
        for (int nt = 0; nt < 8; nt++) {
            float2 mv0 = *(const float2*)&mrowA[s0 + nt * 8 + 2 * lc];
            float2 mv1 = *(const float2*)&mrowB[s0 + nt * 8 + 2 * lc];
            sc[nt][0] = sc[nt][0] * 0.125f + mv0.x;
            sc[nt][1] = sc[nt][1] * 0.125f + mv0.y;
            sc[nt][2] = sc[nt][2] * 0.125f + mv1.x;
            sc[nt][3] = sc[nt][3] * 0.125f + mv1.y;
        }

        // online softmax, two row-halves per thread
        #pragma unroll
        for (int half = 0; half < 2; half++) {
            float rm = -INFINITY;
            #pragma unroll
            for (int nt = 0; nt < 8; nt++)
                rm = fmaxf(rm, fmaxf(sc[nt][2 * half], sc[nt][2 * half + 1]));
            rm = fmaxf(rm, __shfl_xor_sync(0xffffffffu, rm, 1));
            rm = fmaxf(rm, __shfl_xor_sync(0xffffffffu, rm, 2));
            float mnew = fmaxf(m_i[half], rm);
            float corr = __expf(m_i[half] - mnew);
            float rs = 0.f;
            #pragma unroll
            for (int nt = 0; nt < 8; nt++) {
                float p0 = __expf(sc[nt][2 * half    ] - mnew);
                float p1 = __expf(sc[nt][2 * half + 1] - mnew);
                sc[nt][2 * half] = p0;
                sc[nt][2 * half + 1] = p1;
                rs += p0 + p1;
            }
            rs += __shfl_xor_sync(0xffffffffu, rs, 1);
            rs += __shfl_xor_sync(0xffffffffu, rs, 2);
            l_i[half] = l_i[half] * corr + rs;
            m_i[half] = mnew;
            #pragma unroll
            for (int nt = 0; nt < 8; nt++) {
                o[nt][2 * half] *= corr;
                o[nt][2 * half + 1] *= corr;
            }
        }

        __syncthreads();   // all warps done reading Ks as K

        // store P (tf32) into Ks as [m][s]
        #pragma unroll
        for (int nt = 0; nt < 8; nt++) {
            *(float2*)&Ks[wm + lr    ][nt * 8 + 2 * lc] =
                make_float2(tf32r(sc[nt][0]), tf32r(sc[nt][1]));
            *(float2*)&Ks[wm + lr + 8][nt * 8 + 2 * lc] =
                make_float2(tf32r(sc[nt][2]), tf32r(sc[nt][3]));
        }
        __syncthreads();

        // O += P V
        #pragma unroll
        for (int k8 = 0; k8 < 8; k8++) {
            int s = k8 * 8;
            unsigned pa[4];
            pa[0] = fbits(Ks[wm + lr    ][s + lc    ]);
            pa[1] = fbits(Ks[wm + lr + 8][s + lc    ]);
            pa[2] = fbits(Ks[wm + lr    ][s + lc + 4]);
            pa[3] = fbits(Ks[wm + lr + 8][s + lc + 4]);
            #pragma unroll
            for (int nt = 0; nt < 8; nt++) {
                unsigned b0 = fbits(Vs[s + lc    ][nt * 8 + lr]);
                unsigned b1 = fbits(Vs[s + lc + 4][nt * 8 + lr]);
                mma8(o[nt], pa, b0, b1);
            }
        }
    }

    // finalize: divide by l, write raw O (norm folded in later)
    float inv0 = 1.f / l_i[0];
    float inv1 = 1.f / l_i[1];
    float* Op0 = O + (size_t)(t0 + wm + lr) * HD;
    float* Op1 = Op0 + 8 * HD;
    #pragma unroll
    for (int nt = 0; nt < 8; nt++) {
        *(float2*)&Op0[nt * 8 + 2 * lc] = make_float2(o[nt][0] * inv0, o[nt][1] * inv0);
        *(float2*)&Op1[nt * 8 + 2 * lc] = make_float2(o[nt][2] * inv1, o[nt][3] * inv1);
    }
}

// ============================================================
// Kernel 3: per-head norm partial sums (deterministic 2-stage reduce).
// ============================================================
__global__ __launch_bounds__(256)
void norm_partial()
{
    const int c   = blockIdx.x;
    const int h   = blockIdx.y;
    const int tid = threadIdx.x;
    const int bt  = c * 256 + tid;
    const int b   = bt >> 11;
    const int t   = bt & 2047;

    const float* row = g_O + (size_t)((b * NH + h) * SEQ + t) * HD;
    float ss = 0.f;
    #pragma unroll
    for (int i = 0; i < 16; i++) {
        float4 v = *(const float4*)&row[i * 4];
        ss += v.x * v.x + v.y * v.y + v.z * v.z + v.w * v.w;
    }
    float nrm = sqrtf(ss);

    __shared__ float red[256];
    red[tid] = nrm;
    __syncthreads();
    for (int s = 128; s > 0; s >>= 1) {
        if (tid < s) red[tid] += red[tid + s];
        __syncthreads();
    }
    if (tid == 0) g_partial[h * 16 + c] = red[0];
}

// ============================================================
// Kernel 4: finalize per-head scale and fused output bias.
// ============================================================
__global__ void finalize(const float* __restrict__ gate,
                         const float* __restrict__ b_o)
{
    const int tid = threadIdx.x;   // 1024 threads
    if (tid < NH) {
        float s = 0.f;
        #pragma unroll
        for (int c = 0; c < 16; c++) s += g_partial[tid * 16 + c];
        float denom = fmaxf(s / (float)MROWS, 1e-5f);
        float g = fminf(fmaxf(gate[tid], 0.f), 1.f);
        g_scale[tid] = g / (denom * (float)NH);
    }
    float bsum = 0.f;
    #pragma unroll
    for (int h = 0; h < NH; h++) {
        float g = fminf(fmaxf(gate[h], 0.f), 1.f);
        bsum += g * b_o[h * EMB + tid];
    }
    g_bias[tid] = bsum / (float)NH;
}

// ============================================================
// Kernel 5: output projection GEMM (tf32 tensor cores).
// A[r,k=(h,e)] = g_O[b,h,t,e] * g_scale[h]; B = W_o [1024,1024] linear.
// ============================================================
__global__ __launch_bounds__(256)
void out_gemm(const float* __restrict__ Wo, float* __restrict__ OUTP)
{
    __shared__ float As[128][20];
    __shared__ float Bs[16][136];

    const int m0   = blockIdx.y * 128;
    const int n0   = blockIdx.x * 128;
    const int tid  = threadIdx.x;
    const int warp = tid >> 5;
    const int lane = tid & 31;
    const int lr   = lane >> 2;
    const int lc   = lane & 3;
    const int wm   = (warp >> 2) * 64;
    const int wn   = (warp & 3) * 32;

    float c[4][4][4];
    #pragma unroll
    for (int mt = 0; mt < 4; mt++)
        #pragma unroll
        for (int nt = 0; nt < 4; nt++)
            #pragma unroll
            for (int r = 0; r < 4; r++) c[mt][nt][r] = 0.f;

    for (int k0 = 0; k0 < EMB; k0 += 16) {
        #pragma unroll
        for (int i = 0; i < 2; i++) {
            int f    = tid + i * 256;
            int arow = f >> 2;
            int ac   = (f & 3) * 4;
            int r    = m0 + arow;
            int k    = k0 + ac;
            int hh   = k >> 6;
            float s  = g_scale[hh];
            const float* src = &g_O[(size_t)(((r >> 11) * NH + hh) * SEQ + (r & 2047)) * HD + (k & 63)];
            float4 v = *(const float4*)src;
            As[arow][ac + 0] = tf32r(v.x * s);
            As[arow][ac + 1] = tf32r(v.y * s);
            As[arow][ac + 2] = tf32r(v.z * s);
            As[arow][ac + 3] = tf32r(v.w * s);
        }
        #pragma unroll
        for (int i = 0; i < 2; i++) {
            int f    = tid + i * 256;
            int brow = f >> 5;
            int bc   = (f & 31) * 4;
            float4 v = *(const float4*)&Wo[(size_t)(k0 + brow) * EMB + n0 + bc];
            Bs[brow][bc + 0] = tf32r(v.x);
            Bs[brow][bc + 1] = tf32r(v.y);
            Bs[brow][bc + 2] = tf32r(v.z);
            Bs[brow][bc + 3] = tf32r(v.w);
        }
        __syncthreads();

        #pragma unroll
        for (int kk = 0; kk < 2; kk++) {
            const int klo = kk * 8;
            unsigned a[4][4], bf[4][2];
            #pragma unroll
            for (int mt = 0; mt < 4; mt++) {
                int mr = wm + mt * 16 + lr;
                a[mt][0] = fbits(As[mr    ][klo + lc    ]);
                a[mt][1] = fbits(As[mr + 8][klo + lc    ]);
                a[mt][2] = fbits(As[mr    ][klo + lc + 4]);
                a[mt][3] = fbits(As[mr + 8][klo + lc + 4]);
            }
            #pragma unroll
            for (int nt = 0; nt < 4; nt++) {
                int nn = wn + nt * 8 + lr;
                bf[nt][0] = fbits(Bs[klo + lc    ][nn]);
                bf[nt][1] = fbits(Bs[klo + lc + 4][nn]);
            }
            #pragma unroll
            for (int mt = 0; mt < 4; mt++)
                #pragma unroll
                for (int nt = 0; nt < 4; nt++)
                    mma8(c[mt][nt], a[mt], bf[nt][0], bf[nt][1]);
        }
        __syncthreads();
    }

    #pragma unroll
    for (int mt = 0; mt < 4; mt++) {
        int row0 = m0 + wm + mt * 16 + lr;
        int row1 = row0 + 8;
        #pragma unroll
        for (int nt = 0; nt < 4; nt++) {
            int col = n0 + wn + nt * 8 + 2 * lc;
            float2 v0 = make_float2(c[mt][nt][0] + g_bias[col], c[mt][nt][1] + g_bias[col + 1]);
            float2 v1 = make_float2(c[mt][nt][2] + g_bias[col], c[mt][nt][3] + g_bias[col + 1]);
            *(float2*)&OUTP[(size_t)row0 * EMB + col] = v0;
            *(float2*)&OUTP[(size_t)row1 * EMB + col] = v1;
        }
    }
}

// ============================================================
extern "C" void kernel_launch(void* const* d_in, const int* in_sizes, int n_in,
                              void* d_out, int out_size)
{
    const float* X    = (const float*)d_in[0];
    const float* mask = (const float*)d_in[1];
    const float* Wq   = (const float*)d_in[2];
    const float* bq   = (const float*)d_in[3];
    const float* Wk   = (const float*)d_in[4];
    const float* bk   = (const float*)d_in[5];
    const float* Wv   = (const float*)d_in[6];
    const float* bv   = (const float*)d_in[7];
    const float* Wo   = (const float*)d_in[8];
    const float* bo   = (const float*)d_in[9];
    const float* gate = (const float*)d_in[10];
    float* out        = (float*)d_out;

    qkv_gemm    <<<dim3(EMB / 128, MROWS / 128, 3), 256>>>(X, Wq, bq, Wk, bk, Wv, bv);
    attn_kernel <<<dim3(SEQ / 64, NH, BATCH),       128>>>(mask);
    norm_partial<<<dim3(16, NH),                    256>>>();
    finalize    <<<1, EMB>>>(gate, bo);
    out_gemm    <<<dim3(EMB / 128, MROWS / 128),    256>>>(Wo, out);
}